// round 6
// baseline (speedup 1.0000x reference)
#include <cuda_runtime.h>
#include <cstdint>

// GCN on complete graph + self-loops == per-batch mean pooling -> per-batch
// 4-layer MLP on the mean node feature. No TMA: weights are L2-resident and
// streamed straight to registers via coalesced LDG (high MLP); activations
// live in SMEM (pair-packed, broadcast LDS.128); packed fma.rn.f32x2 accums;
// half-block named barriers between dense layers.

#define ROWS 8
#define NT   256

typedef unsigned long long ull;

__device__ __forceinline__ ull pk(float x, float y) {
    ull r;
    asm("mov.b64 %0, {%1, %2};" : "=l"(r) : "f"(x), "f"(y));
    return r;
}
__device__ __forceinline__ void fma2(ull& c, ull a, ull b) {
    asm("fma.rn.f32x2 %0, %1, %2, %3;" : "=l"(c) : "l"(a), "l"(b), "l"(c));
}
__device__ __forceinline__ float2 upk(ull v) {
    float2 r;
    asm("mov.b64 {%0, %1}, %2;" : "=f"(r.x), "=f"(r.y) : "l"(v));
    return r;
}

// Dense 128->128 for one h-group. Activations pair-packed in smem:
// sIn[p*256 + 2k + e] = act[row 2p+e][k]. Weights streamed via LDG
// (coalesced: one 128B line per warp per k). Two independent packed accums.
__device__ __forceinline__ void denseLDG(const float* __restrict__ sIn,
                                         const float* __restrict__ gW,
                                         float bb, float* __restrict__ sOut,
                                         int col, int h) {
    const ulonglong2* inA = reinterpret_cast<const ulonglong2*>(sIn + (2 * h) * 256);
    const ulonglong2* inB = reinterpret_cast<const ulonglong2*>(sIn + (2 * h + 1) * 256);
    const float* wp = gW + col;
    ull accA = 0ULL, accB = 0ULL;
    #pragma unroll
    for (int kq = 0; kq < 32; kq++) {
        const float w0 = __ldg(wp + (4 * kq + 0) * 128);
        const float w1 = __ldg(wp + (4 * kq + 1) * 128);
        const float w2 = __ldg(wp + (4 * kq + 2) * 128);
        const float w3 = __ldg(wp + (4 * kq + 3) * 128);
        const ulonglong2 a0 = inA[2 * kq], a1 = inA[2 * kq + 1];
        const ulonglong2 b0 = inB[2 * kq], b1 = inB[2 * kq + 1];
        const ull wp0 = pk(w0, w0), wp1 = pk(w1, w1);
        const ull wp2 = pk(w2, w2), wp3 = pk(w3, w3);
        fma2(accA, a0.x, wp0); fma2(accA, a0.y, wp1);
        fma2(accA, a1.x, wp2); fma2(accA, a1.y, wp3);
        fma2(accB, b0.x, wp0); fma2(accB, b0.y, wp1);
        fma2(accB, b1.x, wp2); fma2(accB, b1.y, wp3);
    }
    const float2 vA = upk(accA), vB = upk(accB);
    reinterpret_cast<float2*>(sOut)[(2 * h) * 128 + col] =
        make_float2(fmaxf(vA.x + bb, 0.f), fmaxf(vA.y + bb, 0.f));
    reinterpret_cast<float2*>(sOut)[(2 * h + 1) * 128 + col] =
        make_float2(fmaxf(vB.x + bb, 0.f), fmaxf(vB.y + bb, 0.f));
}

__global__ __launch_bounds__(NT) void gcnn_actor_kernel(
    const float* __restrict__ obs,
    const float* __restrict__ W1,  const float* __restrict__ b1,
    const float* __restrict__ W2,  const float* __restrict__ b2,
    const float* __restrict__ Wm1, const float* __restrict__ bm1,
    const float* __restrict__ Wm2, const float* __restrict__ bm2,
    float* __restrict__ out, int std_off)
{
    __shared__ float sA[ROWS * 128];   // h1, then m
    __shared__ float sB[ROWS * 128];   // h2
    __shared__ float sF[ROWS * 16];    // fbar (raw obs dims), then o / std
    __shared__ float sP[NT];           // tail partials

    const int tid  = threadIdx.x;
    const int col  = tid & 127;
    const int h    = tid >> 7;          // 0/1: owns row pairs 2h, 2h+1
    const int base = blockIdx.x * ROWS;

    // ---- prefetch layer-1 params (independent of everything) ----
    float w1r[14];
    #pragma unroll
    for (int d = 0; d < 14; d++) w1r[d] = __ldg(W1 + d * 128 + col);
    const float b1r = __ldg(b1 + col);

    // ---- fbar: 128 threads, each sums one (row, dim) over 32 nodes ----
    if (tid < 128) {
        const int r = tid >> 4, d = tid & 15;
        const float* p = obs + (size_t)(base + r) * 512 + d;
        float s = 0.f;
        #pragma unroll
        for (int n = 0; n < 32; n++) s += __ldg(p + n * 16);
        sF[r * 16 + d] = s * (1.0f / 32.0f);
    }
    __syncthreads();

    // ---- h1 = relu(fbar @ W1 + b1) -> sA (pair-packed); rows 4h..4h+3 ----
    {
        float acc[4];
        #pragma unroll
        for (int q = 0; q < 4; q++) {
            const int r = 4 * h + q;
            float a = b1r;
            #pragma unroll
            for (int d = 0; d < 14; d++)
                a = fmaf(sF[r * 16 + 2 + d], w1r[d], a);   // feat = obs dims 2..15
            acc[q] = fmaxf(a, 0.f);
        }
        reinterpret_cast<float2*>(sA)[(2 * h) * 128 + col]     = make_float2(acc[0], acc[1]);
        reinterpret_cast<float2*>(sA)[(2 * h + 1) * 128 + col] = make_float2(acc[2], acc[3]);
    }
    // group barrier: each h-group only consumes its own writes
    asm volatile("bar.sync %0, 128;" :: "r"(1 + h) : "memory");

    // ---- h2 = relu(h1 @ W2 + b2) ----
    denseLDG(sA, W2, __ldg(b2 + col), sB, col, h);
    asm volatile("bar.sync %0, 128;" :: "r"(1 + h) : "memory");

    // ---- m = relu(h2 @ Wm1 + bm1) ----
    denseLDG(sB, Wm1, __ldg(bm1 + col), sA, col, h);
    __syncthreads();   // tail reads rows across both groups

    // ---- o = m @ Wm2 + bm2 : 256 threads = 8 rows x 4 cols x 8 k-slices ----
    {
        const int r = tid >> 5, c = (tid >> 3) & 3, s = tid & 7;
        const int pair = r >> 1, e = r & 1;
        const float* wp = Wm2 + c;
        float p = 0.f;
        #pragma unroll
        for (int i = 0; i < 16; i++) {
            const int k = s * 16 + i;
            p = fmaf(sA[pair * 256 + 2 * k + e], __ldg(wp + k * 4), p);
        }
        sP[tid] = p;
    }
    __syncthreads();
    if (tid < ROWS * 4) {
        const int r = tid >> 2, c = tid & 3;
        float o = __ldg(bm2 + c);
        #pragma unroll
        for (int s = 0; s < 8; s++) o += sP[(r << 5) | (c << 3) | s];
        if (c < 2) {
            sF[r * 16 + c] = o;                       // mu channel c
        } else {
            const float t = tanhf(o);
            sF[r * 16 + 8 + (c - 2)] = __expf(-5.0f + 3.5f * (t + 1.0f)); // std
        }
    }
    __syncthreads();

    // ---- write: one float4 per thread, fully coalesced ----
    {
        const int plane = tid >> 7;          // 0 = mu, 1 = std
        const int r = (tid & 127) >> 4;      // 0..7
        const int i = tid & 15;              // 0..15
        const int off = plane ? 8 : 0;
        const float v0 = sF[r * 16 + off + 0];
        const float v1 = sF[r * 16 + off + 1];
        float* dst = out + (plane ? (size_t)std_off : 0) + (size_t)(base + r) * 64;
        reinterpret_cast<float4*>(dst)[i] = make_float4(v0, v1, v0, v1);
    }
}

extern "C" void kernel_launch(void* const* d_in, const int* in_sizes, int n_in,
                              void* d_out, int out_size) {
    const float* obs = (const float*)d_in[0];
    const float* W1  = (const float*)d_in[1];
    const float* b1  = (const float*)d_in[2];
    const float* W2  = (const float*)d_in[3];
    const float* b2  = (const float*)d_in[4];
    const float* Wm1 = (const float*)d_in[5];
    const float* bm1 = (const float*)d_in[6];
    const float* Wm2 = (const float*)d_in[7];
    const float* bm2 = (const float*)d_in[8];
    float* out = (float*)d_out;

    const int bs = in_sizes[0] / 512;
    const int std_off = bs * 64;
    const int grid = bs / ROWS;

    gcnn_actor_kernel<<<grid, NT>>>(obs, W1, b1, W2, b2, Wm1, bm1, Wm2, bm2,
                                    out, std_off);
}

// round 7
// speedup vs baseline: 1.3155x; 1.3155x over previous
#include <cuda_runtime.h>
#include <cstdint>

// GCN on complete graph + self-loops == per-batch mean pooling -> per-batch
// 4-layer MLP on the mean node feature. TMA-staged weights (W2 split in two
// chunks), 256 threads. Dense loops use explicit load-all/use-all chunking
// (32 weight regs per chunk) to force ptxas to batch LDS and hide latency.

#define ROWS 8
#define NT   256

typedef unsigned long long ull;

// ---- smem layout (floats) ----
#define OFF_OBS   0
#define N_OBS     (ROWS * 512)
#define OFF_P     OFF_OBS               // tail scratch after obs is dead
#define OFF_W1    (OFF_OBS + N_OBS)
#define N_W1      (14 * 128)
#define OFF_B1    (OFF_W1 + N_W1)
#define OFF_W2    (OFF_B1 + 128)
#define N_W2      (128 * 128)
#define OFF_B2    (OFF_W2 + N_W2)
#define OFF_WM1   (OFF_B2 + 128)
#define OFF_BM1   (OFF_WM1 + N_W2)
#define OFF_WM2   (OFF_BM1 + 128)
#define N_WM2     (128 * 4)
#define OFF_BM2   (OFF_WM2 + N_WM2)
#define OFF_A     (OFF_BM2 + 4)
#define OFF_B     (OFF_A + ROWS * 128)
#define OFF_F     (OFF_B + ROWS * 128)
#define OFF_MBAR  (OFF_F + ROWS * 16)
#define SMEM_FLOATS (OFF_MBAR + 8)
#define SMEM_BYTES  (SMEM_FLOATS * 4)

#define BYTES_A  ((N_OBS + N_W1 + 128) * 4)
#define BYTES_B0 ((64 * 128) * 4)
#define BYTES_B1 ((64 * 128 + 128) * 4)
#define BYTES_C  ((N_W2 + 128 + N_WM2 + 4) * 4)

__device__ __forceinline__ uint32_t s2u(const void* p) {
    return (uint32_t)__cvta_generic_to_shared(p);
}
__device__ __forceinline__ void mbar_init(uint32_t a, uint32_t cnt) {
    asm volatile("mbarrier.init.shared.b64 [%0], %1;" :: "r"(a), "r"(cnt) : "memory");
}
__device__ __forceinline__ void mbar_expect(uint32_t a, uint32_t bytes) {
    asm volatile("mbarrier.arrive.expect_tx.shared.b64 _, [%0], %1;"
                 :: "r"(a), "r"(bytes) : "memory");
}
__device__ __forceinline__ void bulk_g2s(uint32_t dst, const void* src,
                                         uint32_t bytes, uint32_t mbar) {
    asm volatile("cp.async.bulk.shared::cluster.global.mbarrier::complete_tx::bytes "
                 "[%0], [%1], %2, [%3];"
                 :: "r"(dst), "l"(src), "r"(bytes), "r"(mbar) : "memory");
}
__device__ __forceinline__ void mbar_wait(uint32_t a, uint32_t parity) {
    asm volatile(
        "{\n\t.reg .pred P;\n"
        "WAIT_%=:\n\t"
        "mbarrier.try_wait.parity.shared.b64 P, [%0], %1, 0x989680;\n\t"
        "@P bra.uni DONE_%=;\n\t"
        "bra.uni WAIT_%=;\n"
        "DONE_%=:\n\t}"
        :: "r"(a), "r"(parity) : "memory");
}

// ---- packed f32x2 helpers ----
__device__ __forceinline__ ull pk(float x, float y) {
    ull r;
    asm("mov.b64 %0, {%1, %2};" : "=l"(r) : "f"(x), "f"(y));
    return r;
}
__device__ __forceinline__ void fma2(ull& c, ull a, ull b) {
    asm("fma.rn.f32x2 %0, %1, %2, %3;" : "=l"(c) : "l"(a), "l"(b), "l"(c));
}
__device__ __forceinline__ float2 upk(ull v) {
    float2 r;
    asm("mov.b64 {%0, %1}, %2;" : "=f"(r.x), "=f"(r.y) : "l"(v));
    return r;
}

// CHUNKS x 32-k dense accumulation. Per chunk: load 32 weight scalars into
// registers (independent LDS batch), THEN consume them with activation
// LDS.128 broadcasts + packed FMAs. kq0 indexes activations (4k units).
template<int CHUNKS>
__device__ __forceinline__ void dense_chunks(const ulonglong2* __restrict__ inA,
                                             const ulonglong2* __restrict__ inB,
                                             const float* __restrict__ wCol,
                                             int kq0, ull& accA, ull& accB) {
    #pragma unroll
    for (int ch = 0; ch < CHUNKS; ch++) {
        float w[32];
        #pragma unroll
        for (int i = 0; i < 32; i++) w[i] = wCol[(ch * 32 + i) * 128];
        #pragma unroll
        for (int q = 0; q < 8; q++) {
            const int kq = kq0 + ch * 8 + q;
            const ulonglong2 a0 = inA[2 * kq], a1 = inA[2 * kq + 1];
            const ulonglong2 b0 = inB[2 * kq], b1 = inB[2 * kq + 1];
            const ull wp0 = pk(w[4 * q + 0], w[4 * q + 0]);
            const ull wp1 = pk(w[4 * q + 1], w[4 * q + 1]);
            const ull wp2 = pk(w[4 * q + 2], w[4 * q + 2]);
            const ull wp3 = pk(w[4 * q + 3], w[4 * q + 3]);
            fma2(accA, a0.x, wp0); fma2(accA, a0.y, wp1);
            fma2(accA, a1.x, wp2); fma2(accA, a1.y, wp3);
            fma2(accB, b0.x, wp0); fma2(accB, b0.y, wp1);
            fma2(accB, b1.x, wp2); fma2(accB, b1.y, wp3);
        }
    }
}

__global__ __launch_bounds__(NT) void gcnn_actor_kernel(
    const float* __restrict__ obs,
    const float* __restrict__ W1,  const float* __restrict__ b1,
    const float* __restrict__ W2,  const float* __restrict__ b2,
    const float* __restrict__ Wm1, const float* __restrict__ bm1,
    const float* __restrict__ Wm2, const float* __restrict__ bm2,
    float* __restrict__ out, int std_off)
{
    extern __shared__ float sm[];
    float* sObs = sm + OFF_OBS;
    float* sP   = sm + OFF_P;
    float* sA   = sm + OFF_A;
    float* sB   = sm + OFF_B;
    float* sF   = sm + OFF_F;

    const int tid  = threadIdx.x;
    const int col  = tid & 127;
    const int h    = tid >> 7;           // 0/1: owns row pairs 2h, 2h+1
    const int base = blockIdx.x * ROWS;

    const uint32_t mbarA  = s2u(sm + OFF_MBAR);
    const uint32_t mbarB0 = mbarA + 8;
    const uint32_t mbarB1 = mbarA + 16;
    const uint32_t mbarC  = mbarA + 24;

    if (tid == 0) {
        mbar_init(mbarA, 1); mbar_init(mbarB0, 1);
        mbar_init(mbarB1, 1); mbar_init(mbarC, 1);
    }
    __syncthreads();

    if (tid == 0) {
        mbar_expect(mbarA, BYTES_A);
        bulk_g2s(s2u(sm + OFF_OBS), obs + (size_t)base * 512, N_OBS * 4, mbarA);
        bulk_g2s(s2u(sm + OFF_W1),  W1,  N_W1 * 4,  mbarA);
        bulk_g2s(s2u(sm + OFF_B1),  b1,  128 * 4,   mbarA);
        mbar_expect(mbarB0, BYTES_B0);
        bulk_g2s(s2u(sm + OFF_W2),  W2,  64 * 128 * 4, mbarB0);
        mbar_expect(mbarB1, BYTES_B1);
        bulk_g2s(s2u(sm + OFF_W2 + 64 * 128), W2 + 64 * 128, 64 * 128 * 4, mbarB1);
        bulk_g2s(s2u(sm + OFF_B2),  b2,  128 * 4,   mbarB1);
        mbar_expect(mbarC, BYTES_C);
        bulk_g2s(s2u(sm + OFF_WM1), Wm1, N_W2 * 4,  mbarC);
        bulk_g2s(s2u(sm + OFF_BM1), bm1, 128 * 4,   mbarC);
        bulk_g2s(s2u(sm + OFF_WM2), Wm2, N_WM2 * 4, mbarC);
        bulk_g2s(s2u(sm + OFF_BM2), bm2, 4 * 4,     mbarC);
    }

    // ---- obs + layer-1 params ----
    mbar_wait(mbarA, 0);

    // fbar: 128 threads, thread (r = tid>>4, d = tid&15), feature dims 2..15
    if (tid < 128) {
        const int r = tid >> 4, d = tid & 15;
        if (d < 14) {
            float s = 0.f;
            #pragma unroll
            for (int n = 0; n < 32; n++) s += sObs[r * 512 + n * 16 + 2 + d];
            sF[r * 16 + d] = s * (1.0f / 32.0f);
        }
    }
    __syncthreads();

    // h1 = relu(fbar @ W1 + b1) -> sA (pair-packed); thread does rows 4h..4h+3
    {
        float w[14];
        #pragma unroll
        for (int d = 0; d < 14; d++) w[d] = sm[OFF_W1 + d * 128 + col];
        const float bb = sm[OFF_B1 + col];
        float acc[4];
        #pragma unroll
        for (int q = 0; q < 4; q++) {
            const int r = 4 * h + q;
            float a = bb;
            #pragma unroll
            for (int d = 0; d < 14; d++) a = fmaf(sF[r * 16 + d], w[d], a);
            acc[q] = fmaxf(a, 0.f);
        }
        reinterpret_cast<float2*>(sA)[(2 * h) * 128 + col]     = make_float2(acc[0], acc[1]);
        reinterpret_cast<float2*>(sA)[(2 * h + 1) * 128 + col] = make_float2(acc[2], acc[3]);
    }
    asm volatile("bar.sync %0, 128;" :: "r"(1 + h) : "memory");

    const ulonglong2* inA2 = reinterpret_cast<const ulonglong2*>(sA + (2 * h) * 256);
    const ulonglong2* inB2 = reinterpret_cast<const ulonglong2*>(sA + (2 * h + 1) * 256);

    // ---- layer 2: h2 = relu(h1 @ W2 + b2), W2 streamed in two TMA chunks ----
    {
        ull accA = 0ULL, accB = 0ULL;
        mbar_wait(mbarB0, 0);
        dense_chunks<2>(inA2, inB2, sm + OFF_W2 + col, 0, accA, accB);
        mbar_wait(mbarB1, 0);
        dense_chunks<2>(inA2, inB2, sm + OFF_W2 + 64 * 128 + col, 16, accA, accB);
        const float bb = sm[OFF_B2 + col];
        const float2 vA = upk(accA), vB = upk(accB);
        reinterpret_cast<float2*>(sB)[(2 * h) * 128 + col] =
            make_float2(fmaxf(vA.x + bb, 0.f), fmaxf(vA.y + bb, 0.f));
        reinterpret_cast<float2*>(sB)[(2 * h + 1) * 128 + col] =
            make_float2(fmaxf(vB.x + bb, 0.f), fmaxf(vB.y + bb, 0.f));
    }
    asm volatile("bar.sync %0, 128;" :: "r"(1 + h) : "memory");

    // ---- layer 3: m = relu(h2 @ Wm1 + bm1) ----
    {
        const ulonglong2* inA3 = reinterpret_cast<const ulonglong2*>(sB + (2 * h) * 256);
        const ulonglong2* inB3 = reinterpret_cast<const ulonglong2*>(sB + (2 * h + 1) * 256);
        ull accA = 0ULL, accB = 0ULL;
        mbar_wait(mbarC, 0);
        dense_chunks<4>(inA3, inB3, sm + OFF_WM1 + col, 0, accA, accB);
        const float bb = sm[OFF_BM1 + col];
        const float2 vA = upk(accA), vB = upk(accB);
        reinterpret_cast<float2*>(sA)[(2 * h) * 128 + col] =
            make_float2(fmaxf(vA.x + bb, 0.f), fmaxf(vA.y + bb, 0.f));
        reinterpret_cast<float2*>(sA)[(2 * h + 1) * 128 + col] =
            make_float2(fmaxf(vB.x + bb, 0.f), fmaxf(vB.y + bb, 0.f));
    }
    __syncthreads();   // tail reads rows across both groups

    // ---- o = m @ Wm2 + bm2 : 256 threads = 8 rows x 4 cols x 8 k-slices ----
    {
        const int r = tid >> 5, c = (tid >> 3) & 3, s = tid & 7;
        const int pair = r >> 1, e = r & 1;
        float p = 0.f;
        #pragma unroll
        for (int i = 0; i < 16; i++) {
            const int k = s * 16 + i;
            p = fmaf(sA[pair * 256 + 2 * k + e], sm[OFF_WM2 + k * 4 + c], p);
        }
        sP[tid] = p;
    }
    __syncthreads();
    if (tid < ROWS * 4) {
        const int r = tid >> 2, c = tid & 3;
        float o = sm[OFF_BM2 + c];
        #pragma unroll
        for (int s = 0; s < 8; s++) o += sP[(r << 5) | (c << 3) | s];
        if (c < 2) {
            sF[r * 16 + c] = o;                                   // mu
        } else {
            const float t = tanhf(o);
            sF[r * 16 + 8 + (c - 2)] = __expf(-5.0f + 3.5f * (t + 1.0f)); // std
        }
    }
    __syncthreads();

    // ---- write: one float4 per thread, fully coalesced ----
    {
        const int plane = tid >> 7;          // 0 = mu, 1 = std
        const int r = (tid & 127) >> 4;      // 0..7
        const int i = tid & 15;              // 0..15
        const int off = plane ? 8 : 0;
        const float v0 = sF[r * 16 + off + 0];
        const float v1 = sF[r * 16 + off + 1];
        float* dst = out + (plane ? (size_t)std_off : 0) + (size_t)(base + r) * 64;
        reinterpret_cast<float4*>(dst)[i] = make_float4(v0, v1, v0, v1);
    }
}

extern "C" void kernel_launch(void* const* d_in, const int* in_sizes, int n_in,
                              void* d_out, int out_size) {
    const float* obs = (const float*)d_in[0];
    const float* W1  = (const float*)d_in[1];
    const float* b1  = (const float*)d_in[2];
    const float* W2  = (const float*)d_in[3];
    const float* b2  = (const float*)d_in[4];
    const float* Wm1 = (const float*)d_in[5];
    const float* bm1 = (const float*)d_in[6];
    const float* Wm2 = (const float*)d_in[7];
    const float* bm2 = (const float*)d_in[8];
    float* out = (float*)d_out;

    const int bs = in_sizes[0] / 512;
    const int std_off = bs * 64;
    const int grid = bs / ROWS;

    cudaFuncSetAttribute(gcnn_actor_kernel,
                         cudaFuncAttributeMaxDynamicSharedMemorySize, SMEM_BYTES);
    gcnn_actor_kernel<<<grid, NT, SMEM_BYTES>>>(obs, W1, b1, W2, b2, Wm1, bm1,
                                                Wm2, bm2, out, std_off);
}